// round 15
// baseline (speedup 1.0000x reference)
#include <cuda_runtime.h>

#define NUM_LEVELS 256

__device__ __forceinline__ float quantize_one(float v) {
    // Nearest center of linspace(-1, 1, 256): i = round((v+1)*127.5), clamp [0,255].
    // Round-to-nearest-even via magic-number add/sub (4-cyc FMA pipe, no cvt pipe).
    float t = fmaf(v, 127.5f, 127.5f);
    t = fmaxf(0.0f, fminf(255.0f, t));
    const float MAGIC = 12582912.0f;            // 1.5 * 2^23
    float r = (t + MAGIC) - MAGIC;              // rint(t) for 0 <= t <= 255
    return fmaf(r, 2.0f / 255.0f, -1.0f);       // center = -1 + i * (2/255)
}

// 256-bit global load/store (sm_100+: LDG.E.256 / STG.E.256).
__device__ __forceinline__ void ldg_v8(const float* __restrict__ p, float r[8]) {
    asm volatile("ld.global.v8.f32 {%0,%1,%2,%3,%4,%5,%6,%7}, [%8];"
                 : "=f"(r[0]), "=f"(r[1]), "=f"(r[2]), "=f"(r[3]),
                   "=f"(r[4]), "=f"(r[5]), "=f"(r[6]), "=f"(r[7])
                 : "l"(p));
}
__device__ __forceinline__ void stg_v8(float* __restrict__ p, const float r[8]) {
    asm volatile("st.global.v8.f32 [%0], {%1,%2,%3,%4,%5,%6,%7,%8};"
                 :: "l"(p),
                    "f"(r[0]), "f"(r[1]), "f"(r[2]), "f"(r[3]),
                    "f"(r[4]), "f"(r[5]), "f"(r[6]), "f"(r[7])
                 : "memory");
}

// Exact-fit variant: grid*block == n8, no predicate, no index clamp.
// SASS body: IMAD (addr) -> LDG.E.256 -> 8x(FFMA,FADD,FADD,FMNMX,FMNMX,FFMA) -> STG.E.256 -> EXIT
__global__ void __launch_bounds__(256) nq_kernel_v8_exact(
    const float* __restrict__ x,
    float* __restrict__ out)
{
    size_t idx = (size_t)blockIdx.x * blockDim.x + threadIdx.x;
    float r[8];
    ldg_v8(x + idx * 8, r);
    #pragma unroll
    for (int k = 0; k < 8; k++) r[k] = quantize_one(r[k]);
    stg_v8(out + idx * 8, r);
}

// Guarded variant for sizes that don't divide evenly.
__global__ void __launch_bounds__(256) nq_kernel_v8(
    const float* __restrict__ x,
    float* __restrict__ out,
    int n8)
{
    int idx = blockIdx.x * blockDim.x + threadIdx.x;
    if (idx < n8) {
        float r[8];
        ldg_v8(x + (size_t)idx * 8, r);
        #pragma unroll
        for (int k = 0; k < 8; k++) r[k] = quantize_one(r[k]);
        stg_v8(out + (size_t)idx * 8, r);
    }
}

__global__ void __launch_bounds__(256) nq_tail_kernel(
    const float* __restrict__ x,
    float* __restrict__ out,
    int start, int n)
{
    int i = start + blockIdx.x * blockDim.x + threadIdx.x;
    if (i < n) out[i] = quantize_one(x[i]);
}

extern "C" void kernel_launch(void* const* d_in, const int* in_sizes, int n_in,
                              void* d_out, int out_size) {
    const float* x = (const float*)d_in[0];
    float* out = (float*)d_out;
    int n = in_sizes[0];

    const int threads = 256;
    int n8 = n / 8;
    if (n8 > 0) {
        if (n8 % threads == 0) {
            // Exact fit: branch-free kernel body (n = 2^21 -> 1024 blocks).
            nq_kernel_v8_exact<<<n8 / threads, threads>>>(x, out);
        } else {
            nq_kernel_v8<<<(n8 + threads - 1) / threads, threads>>>(x, out, n8);
        }
    }
    int tail_start = n8 * 8;
    int tail = n - tail_start;
    if (tail > 0) {
        nq_tail_kernel<<<1, 256>>>(x, out, tail_start, n);
    }
}

// round 16
// speedup vs baseline: 1.0386x; 1.0386x over previous
#include <cuda_runtime.h>

#define NUM_LEVELS 256

__device__ __forceinline__ float quantize_one(float v) {
    // Nearest center of linspace(-1, 1, 256): i = round((v+1)*127.5), clamp [0,255].
    // Round-to-nearest-even via magic-number add/sub (4-cyc FMA pipe, no cvt pipe).
    float t = fmaf(v, 127.5f, 127.5f);
    t = fmaxf(0.0f, fminf(255.0f, t));
    const float MAGIC = 12582912.0f;            // 1.5 * 2^23
    float r = (t + MAGIC) - MAGIC;              // rint(t) for 0 <= t <= 255
    return fmaf(r, 2.0f / 255.0f, -1.0f);       // center = -1 + i * (2/255)
}

// 256-bit global load/store (sm_100+: LDG.E.256 / STG.E.256).
__device__ __forceinline__ void ldg_v8(const float* __restrict__ p, float r[8]) {
    asm volatile("ld.global.v8.f32 {%0,%1,%2,%3,%4,%5,%6,%7}, [%8];"
                 : "=f"(r[0]), "=f"(r[1]), "=f"(r[2]), "=f"(r[3]),
                   "=f"(r[4]), "=f"(r[5]), "=f"(r[6]), "=f"(r[7])
                 : "l"(p));
}
__device__ __forceinline__ void stg_v8(float* __restrict__ p, const float r[8]) {
    asm volatile("st.global.v8.f32 [%0], {%1,%2,%3,%4,%5,%6,%7,%8};"
                 :: "l"(p),
                    "f"(r[0]), "f"(r[1]), "f"(r[2]), "f"(r[3]),
                    "f"(r[4]), "f"(r[5]), "f"(r[6]), "f"(r[7])
                 : "memory");
}

// One float8 per thread; 128-thread blocks for finest CTA placement granularity.
__global__ void __launch_bounds__(128) nq_kernel_v8(
    const float* __restrict__ x,
    float* __restrict__ out,
    int n8)
{
    int idx = blockIdx.x * blockDim.x + threadIdx.x;
    if (idx < n8) {
        float r[8];
        ldg_v8(x + (size_t)idx * 8, r);
        #pragma unroll
        for (int k = 0; k < 8; k++) r[k] = quantize_one(r[k]);
        stg_v8(out + (size_t)idx * 8, r);
    }
}

__global__ void __launch_bounds__(128) nq_tail_kernel(
    const float* __restrict__ x,
    float* __restrict__ out,
    int start, int n)
{
    int i = start + blockIdx.x * blockDim.x + threadIdx.x;
    if (i < n) out[i] = quantize_one(x[i]);
}

extern "C" void kernel_launch(void* const* d_in, const int* in_sizes, int n_in,
                              void* d_out, int out_size) {
    const float* x = (const float*)d_in[0];
    float* out = (float*)d_out;
    int n = in_sizes[0];

    const int threads = 128;
    int n8 = n / 8;
    if (n8 > 0) {
        int blocks = (n8 + threads - 1) / threads;   // 2048 blocks for n = 2^21
        nq_kernel_v8<<<blocks, threads>>>(x, out, n8);
    }
    int tail_start = n8 * 8;
    int tail = n - tail_start;
    if (tail > 0) {
        nq_tail_kernel<<<1, threads>>>(x, out, tail_start, n);
    }
}